// round 16
// baseline (speedup 1.0000x reference)
#include <cuda_runtime.h>
#include <cuda_bf16.h>
#include <cstdint>

// Nearest-of-16-sorted-qpoints quantizer — FINAL (R11 configuration).
// Session-converged floor: 512 MiB irreducible r+w traffic at the mixed
// read/write HBM3e ceiling (~6.95 TB/s demand, DRAM pipe ~78-79%, kernel
// ~77.5us across every sane config). This config held the best bench
// sample (80.35us) with near-best ncu time and highest occupancy margin.
//   - 256 thr/block, 2x float4/thread, 32768 blocks, 31 regs, occ ~85%
//   - 4-level branchless LDS binary search (idx = #{j : x > mid[j]},
//     ties -> left point; rel_err == 0 in all 12 rounds)
//   - L1::no_allocate on both load and store streams (read/write-once data)

__device__ __forceinline__ float quant1(float v, float m7,
                                        const float* __restrict__ s_mid,
                                        const float* __restrict__ s_qp)
{
    int i = (v > m7) ? 8 : 0;              // level 0: uniform register compare
    i += (v > s_mid[i + 3]) ? 4 : 0;       // level 1: LDS
    i += (v > s_mid[i + 1]) ? 2 : 0;       // level 2: LDS
    i += (v > s_mid[i]) ? 1 : 0;           // level 3: LDS
    return s_qp[i];                         // value LUT: LDS broadcast
}

// 128-bit streaming load, no L1 allocation.
__device__ __forceinline__ float4 ldg128_noL1(const float4* p)
{
    float4 r;
    asm volatile(
        "ld.global.L1::no_allocate.v4.f32 {%0,%1,%2,%3}, [%4];"
        : "=f"(r.x), "=f"(r.y), "=f"(r.z), "=f"(r.w)
        : "l"(p));
    return r;
}

// 128-bit streaming store, no L1 allocation.
__device__ __forceinline__ void stg128_noL1(float4* p, float4 v)
{
    asm volatile(
        "st.global.L1::no_allocate.v4.f32 [%0], {%1,%2,%3,%4};"
        :: "l"(p), "f"(v.x), "f"(v.y), "f"(v.z), "f"(v.w)
        : "memory");
}

__global__ __launch_bounds__(256) void QPointQuantize_kernel(
    const float4* __restrict__ x,
    const float* __restrict__ q,
    float4* __restrict__ out,
    int n4)
{
    __shared__ float s_qp[16];
    __shared__ float s_mid[16];   // 15 used; banks 0-14, conflict-free

    // One-stage init straight from global q (16 B, L2-resident after warp 0).
    if (threadIdx.x < 16) {
        float qi = q[threadIdx.x];
        s_qp[threadIdx.x] = qi;
        if (threadIdx.x < 15)
            s_mid[threadIdx.x] = 0.5f * (qi + q[threadIdx.x + 1]);
    }
    __syncthreads();

    const float m7 = s_mid[7];    // uniform -> register, skips one LDS level

    // 2 float4 per thread, coalesced, front-batched loads (MLP_p1=2).
    int base = blockIdx.x * (256 * 2) + threadIdx.x;

    if (base + 256 < n4) {        // taken by every live block for this shape
        float4 v0 = ldg128_noL1(&x[base]);
        float4 v1 = ldg128_noL1(&x[base + 256]);

        float4 o0, o1;
        o0.x = quant1(v0.x, m7, s_mid, s_qp);
        o0.y = quant1(v0.y, m7, s_mid, s_qp);
        o0.z = quant1(v0.z, m7, s_mid, s_qp);
        o0.w = quant1(v0.w, m7, s_mid, s_qp);
        o1.x = quant1(v1.x, m7, s_mid, s_qp);
        o1.y = quant1(v1.y, m7, s_mid, s_qp);
        o1.z = quant1(v1.z, m7, s_mid, s_qp);
        o1.w = quant1(v1.w, m7, s_mid, s_qp);

        stg128_noL1(&out[base],       o0);
        stg128_noL1(&out[base + 256], o1);
    } else {
        // Cold tail fallback (unreached for 64x1024x1024, kept for safety)
        for (int k = 0; k < 2; k++) {
            int idx = base + k * 256;
            if (idx < n4) {
                float4 v = ldg128_noL1(&x[idx]);
                float4 o;
                o.x = quant1(v.x, m7, s_mid, s_qp);
                o.y = quant1(v.y, m7, s_mid, s_qp);
                o.z = quant1(v.z, m7, s_mid, s_qp);
                o.w = quant1(v.w, m7, s_mid, s_qp);
                stg128_noL1(&out[idx], o);
            }
        }
    }
}

extern "C" void kernel_launch(void* const* d_in, const int* in_sizes, int n_in,
                              void* d_out, int out_size)
{
    const float* x = (const float*)d_in[0];   // (64, 1024, 1024) fp32
    const float* q = (const float*)d_in[1];   // (16,) fp32 sorted
    float* out = (float*)d_out;

    int n = in_sizes[0];          // 67,108,864
    int n4 = n >> 2;              // 16,777,216 float4s

    int threads = 256;
    int elems_per_block = threads * 2;                     // 512 float4s
    int blocks = (n4 + elems_per_block - 1) / elems_per_block;  // 32,768

    QPointQuantize_kernel<<<blocks, threads>>>(
        (const float4*)x, q, (float4*)out, n4);
}